// round 12
// baseline (speedup 1.0000x reference)
#include <cuda_runtime.h>
#include <math.h>

#define NPFS  4
#define NF    512
#define NP    256
#define BATCH 128
#define NMAT  (BATCH * NPFS)            // 512 matrices
#define NTHR  1024
#define NW    (NTHR / 32)               // 32 warps

// padded, 16B-aligned row bases for the lower triangle
__device__ __host__ __forceinline__ unsigned rowb(int r) {
    return ((unsigned)((r * (r - 1)) / 2 + 6 * r)) & ~3u;
}
#define L_ELEMS 34176                    // >= rowb(255) + 260, mult of 4

// Scratch (__device__ globals — allocations forbidden)
__device__ float g_sign[NMAT];
__device__ float g_logabs[NMAT];

// reduce (absmax, signed value, lowest index on ties) within a warp
__device__ __forceinline__ void wred3(float& bv, float& sv, int& bi) {
    #pragma unroll
    for (int off = 16; off; off >>= 1) {
        float ov = __shfl_down_sync(0xffffffffu, bv, off);
        float os = __shfl_down_sync(0xffffffffu, sv, off);
        int   oi = __shfl_down_sync(0xffffffffu, bi, off);
        if (ov > bv || (ov == bv && oi < bi)) { bv = ov; sv = os; bi = oi; }
    }
}

// ---------------------------------------------------------------------------
// Kernel: one CTA per matrix. Lower triangle (padded rows) in smem.
// Parlett-Reid with partial pivoting, TWO steps fused into ONE rank-4 pass.
// 3 barriers per double-step. Column caches are split into X (colA/colB:
// read-only in phase BC, written by phase E / gather) and Y (colAn/colBn/
// colBr: written by BC, read by D) so no scalar is read and written in the
// same phase. Dead swap writes (row kp1 cols<=k3; whole col kp1 if kp1<=k3)
// are skipped, making the remaining raw reads race-free.
// ---------------------------------------------------------------------------
__global__ __launch_bounds__(NTHR, 1)
void pf_kernel(const float* __restrict__ F, const int* __restrict__ idx) {
    extern __shared__ float sm[];
    float* L     = sm;                  // [L_ELEMS]
    float* tau1  = sm + L_ELEMS;        // [NP]
    float* v1    = tau1 + NP;           // [NP]
    float* tau2  = v1 + NP;             // [NP]
    float* v2    = tau2 + NP;           // [NP]
    float* tau1p = v2 + NP;             // [NP]  swap-b-permuted tau1
    float* v1p   = tau1p + NP;          // [NP]
    float* colA  = v1p + NP;            // [NP]  X: column k   at step start
    float* colB  = colA + NP;           // [NP]  X: column k+1 at step start
    float* colAn = colB + NP;           // [NP]  Y: updated column k+2
    float* colBn = colAn + NP;          // [NP]  Y: updated column k+3
    float* colBr = colBn + NP;          // [NP]  Y: raw column k+3 (pre-update-1)

    __shared__ int   s_idx[NP];
    __shared__ float s_rv[NW];
    __shared__ float s_sv[NW];
    __shared__ int   s_ri[NW];

    const int tid  = threadIdx.x;
    const int lane = tid & 31;
    const int wid  = tid >> 5;
    const int m    = blockIdx.x;
    const int b    = m >> 2;
    const int p    = m & 3;

    if (tid < NP) s_idx[tid] = idx[b * NP + tid];
    __syncthreads();

    // ---- gather (warp per row), antisym fused, + X col cache + pivot scan ----
    {
        float bv = -1.f, sv = 0.f; int bi = NP;
        const float* Fp = F + ((size_t)p << 18);
        for (int r = wid; r < NP; r += NW) {
            const int ir = s_idx[r];
            const float* rowp = Fp + ((size_t)ir << 9);
            unsigned base = rowb(r);
            for (int c = lane; c < r; c += 32) {
                const int ic = s_idx[c];
                float val = 0.5f * (__ldg(&rowp[ic]) - __ldg(&Fp[((size_t)ic << 9) + ir]));
                L[base + c] = val;
                if (c == 0) {
                    colA[r] = val;
                    float a = fabsf(val);
                    if (a > bv || (a == bv && r < bi)) { bv = a; sv = val; bi = r; }
                }
                if (c == 1) colB[r] = val;
            }
        }
        wred3(bv, sv, bi);
        if (lane == 0) { s_rv[wid] = bv; s_sv[wid] = sv; s_ri[wid] = bi; }
    }
    __syncthreads();

    float sign = 1.f, logabs = 0.f;   // live in thread 0

    for (int k = 0; k < NP; k += 4) {
        const int p1 = k + 1;
        const int k2 = k + 2;
        const int k3 = k + 3;
        const int k4 = k + 4;
        const int k5 = k + 5;

        // ---- phase A: reduce pivot-a candidates (butterfly over NW) ----
        float pv = s_rv[lane & (NW - 1)];
        float ps = s_sv[lane & (NW - 1)];
        int   pi = s_ri[lane & (NW - 1)];
        #pragma unroll
        for (int off = NW / 2; off; off >>= 1) {
            float ov = __shfl_xor_sync(0xffffffffu, pv, off);
            float os = __shfl_xor_sync(0xffffffffu, ps, off);
            int   oi = __shfl_xor_sync(0xffffffffu, pi, off);
            if (ov > pv || (ov == pv && oi < pi)) { pv = ov; ps = os; pi = oi; }
        }
        const int   kp1  = pi;                 // pivot-a row in (k, NP)
        const float piv1 = -ps;                // post-swap A[k][k+1] = -colA[kp1]
        if (tid == 0) {
            if (kp1 != p1)  sign = -sign;
            if (piv1 < 0.f) sign = -sign;
            logabs += logf(fabsf(piv1));
        }

        // ---- phase BC (merged): tau1/v1 + live swap-a (dead writes skipped)
        //      + updated columns k2,k3 into Y + pivot-b scan ----
        {
            float bv = -1.f, sv = 0.f; int bi = NP;
            if (tid >= k2 && tid < NP) {
                const int t = tid;
                const float rp = 1.0f / piv1;
                const float ta = (t == kp1 ? colA[p1] : colA[t]) * rp;
                const bool kp1_low = (kp1 <= k3);   // col kp1 dead after BC
                float vv;
                if (kp1 != p1) {
                    if (t < kp1) {
                        vv = -L[rowb(kp1) + t];
                        if (t > k3) L[rowb(kp1) + t] = -colB[t];  // skip dead cols k2,k3
                    } else if (t == kp1) {
                        vv = -colB[kp1];
                    } else {
                        vv = L[rowb(t) + kp1];
                        if (!kp1_low) L[rowb(t) + kp1] = colB[t]; // skip dead col kp1
                    }
                } else {
                    vv = colB[t];
                }
                tau1[t] = ta;
                v1[t]   = vv;

                if (t >= k3) {
                    // cross-thread scalars recomputed locally from X/L (race-free)
                    const float t1k2 = (k2 == kp1 ? colA[p1] : colA[k2]) * rp;
                    const float t1k3 = (k3 == kp1 ? colA[p1] : colA[k3]) * rp;
                    float v1k2, v1k3;
                    if (kp1 == p1) {
                        v1k2 = colB[k2];
                        v1k3 = colB[k3];
                    } else {
                        v1k2 = (kp1 > k2) ? -L[rowb(kp1) + k2] : -colB[kp1];
                        v1k3 = (kp1 > k3) ? -L[rowb(kp1) + k3]
                             : (kp1 == k3) ? -colB[kp1]
                             : L[rowb(k3) + k2];               // kp1 == k2
                    }
                    float rawx, rawy;   // A_a[t][k2], A_a[t][k3]
                    if (t == kp1) {
                        rawx = -colB[k2];
                        rawy = -colB[k3];
                    } else {
                        float2 rw = *(const float2*)&L[rowb(t) + k2];
                        rawx = (kp1 == k2) ? colB[t] : rw.x;   // skipped write value
                        rawy = (kp1 == k3) ? colB[t] : rw.y;
                    }
                    const float ca = rawx + vv * t1k2 - ta * v1k2;   // A'[t][k2]
                    const float cb = rawy + vv * t1k3 - ta * v1k3;   // A'[t][k3]
                    colAn[t] = ca;
                    colBn[t] = cb;
                    colBr[t] = rawy;
                    bv = fabsf(ca); sv = ca; bi = t;
                }
            }
            wred3(bv, sv, bi);
            if (lane == 0) { s_rv[wid] = bv; s_sv[wid] = sv; s_ri[wid] = bi; }
        }
        __syncthreads();

        // ---- phase D: pivot-b reduce; tau2/v2 fill + swap-b (raw writes);
        //      permuted tau1p/v1p ----
        pv = s_rv[lane & (NW - 1)];
        ps = s_sv[lane & (NW - 1)];
        pi = s_ri[lane & (NW - 1)];
        #pragma unroll
        for (int off = NW / 2; off; off >>= 1) {
            float ov = __shfl_xor_sync(0xffffffffu, pv, off);
            float os = __shfl_xor_sync(0xffffffffu, ps, off);
            int   oi = __shfl_xor_sync(0xffffffffu, pi, off);
            if (ov > pv || (ov == pv && oi < pi)) { pv = ov; ps = os; pi = oi; }
        }
        const int   kp2  = pi;                 // pivot-b row in (k2, NP)
        const float piv2 = -ps;                // post-swap A'[k2][k3] = -colAn[kp2]
        if (tid == 0) {
            if (kp2 != k3)  sign = -sign;
            if (piv2 < 0.f) sign = -sign;
            logabs += logf(fabsf(piv2));
        }
        if (tid >= k4 && tid < NP) {
            const int t = tid;
            const float rp2 = 1.0f / piv2;
            const float ta = (t == kp2 ? colAn[k3] : colAn[t]) * rp2;
            float vv;
            if (kp2 != k3) {
                if (t < kp2) {
                    vv = -(L[rowb(kp2) + t] + v1[kp2] * tau1[t] - tau1[kp2] * v1[t]);
                    L[rowb(kp2) + t] = -colBr[t];            // raw swap write
                } else if (t == kp2) {
                    vv = -colBn[kp2];                        // -A'[kp2][k3]
                } else {
                    vv = L[rowb(t) + kp2] + v1[t] * tau1[kp2] - tau1[t] * v1[kp2];
                    L[rowb(t) + kp2] = colBr[t];             // raw swap write
                }
            } else {
                vv = colBn[t];
            }
            tau2[t] = ta;
            v2[t]   = vv;
            tau1p[t] = (t == kp2) ? tau1[k3] : tau1[t];      // P-permuted step-1 vectors
            v1p[t]   = (t == kp2) ? v1[k3]   : v1[t];
        }
        __syncthreads();

        // ---- phase E: ONE rank-4 trailing pass, 4 rows per warp;
        //      extraction writes X (cols k4,k5) for the next double-step ----
        if (k4 < NP) {
            float bv = -1.f, sv = 0.f; int bi = NP;
            const int cstart = k4;   // k % 4 == 0 -> 16B aligned
            for (int pr = wid; ; pr += 2 * NW) {
                const int r0 = k5 + 2 * pr;
                if (r0 >= NP) break;
                const int r1 = r0 + 1;
                const int r2 = r0 + 2 * NW;
                const int r3 = r2 + 1;
                const bool ok1 = r1 < NP, ok2 = r2 < NP, ok3 = r3 < NP;

                const unsigned b0 = rowb(r0);
                const unsigned b1 = ok1 ? rowb(r1) : 0u;
                const unsigned b2 = ok2 ? rowb(r2) : 0u;
                const unsigned b3 = ok3 ? rowb(r3) : 0u;
                const int e0 = (r0 + 3) & ~3;
                const int e1 = ok1 ? ((r1 + 3) & ~3) : 0;
                const int e2 = ok2 ? ((r2 + 3) & ~3) : 0;
                const int e3 = ok3 ? ((r3 + 3) & ~3) : 0;
                int emax = e0;
                if (e1 > emax) emax = e1;
                if (e2 > emax) emax = e2;
                if (e3 > emax) emax = e3;

                const float t0 = tau1p[r0], w0 = v1p[r0];
                const float u0 = tau2[r0],  z0 = v2[r0];
                const float t1r = ok1 ? tau1p[r1] : 0.f, w1r = ok1 ? v1p[r1] : 0.f;
                const float u1r = ok1 ? tau2[r1]  : 0.f, z1r = ok1 ? v2[r1]  : 0.f;
                const float t2r = ok2 ? tau1p[r2] : 0.f, w2r = ok2 ? v1p[r2] : 0.f;
                const float u2r = ok2 ? tau2[r2]  : 0.f, z2r = ok2 ? v2[r2]  : 0.f;
                const float t3r = ok3 ? tau1p[r3] : 0.f, w3r = ok3 ? v1p[r3] : 0.f;
                const float u3r = ok3 ? tau2[r3]  : 0.f, z3r = ok3 ? v2[r3]  : 0.f;

                for (int cc = cstart + 4 * lane; cc < emax; cc += 128) {
                    const float4 t1c = *(const float4*)&tau1p[cc];
                    const float4 w1c = *(const float4*)&v1p[cc];
                    const float4 t2c = *(const float4*)&tau2[cc];
                    const float4 w2c = *(const float4*)&v2[cc];

                    #define ROW_UPD(BX, EX, TR, WR, UR, ZR, RX)                          \
                    if (cc < EX) {                                                       \
                        float4 x = *(const float4*)&L[BX + cc];                          \
                        x.x += WR * t1c.x - TR * w1c.x + ZR * t2c.x - UR * w2c.x;        \
                        x.y += WR * t1c.y - TR * w1c.y + ZR * t2c.y - UR * w2c.y;        \
                        x.z += WR * t1c.z - TR * w1c.z + ZR * t2c.z - UR * w2c.z;        \
                        x.w += WR * t1c.w - TR * w1c.w + ZR * t2c.w - UR * w2c.w;        \
                        *(float4*)&L[BX + cc] = x;                                       \
                        if (cc == cstart) {                                              \
                            colA[RX] = x.x; colB[RX] = x.y;                              \
                            float a_ = fabsf(x.x);                                       \
                            if (a_ > bv || (a_ == bv && (RX) < bi)) {                    \
                                bv = a_; sv = x.x; bi = RX;                              \
                            }                                                            \
                        }                                                                \
                    }

                    ROW_UPD(b0, e0, t0,  w0,  u0,  z0,  r0)
                    ROW_UPD(b1, e1, t1r, w1r, u1r, z1r, r1)
                    ROW_UPD(b2, e2, t2r, w2r, u2r, z2r, r2)
                    ROW_UPD(b3, e3, t3r, w3r, u3r, z3r, r3)
                    #undef ROW_UPD
                }
            }
            wred3(bv, sv, bi);
            if (lane == 0) { s_rv[wid] = bv; s_sv[wid] = sv; s_ri[wid] = bi; }
        }
        __syncthreads();
    }

    if (tid == 0) { g_sign[m] = sign; g_logabs[m] = logabs; }
}

// ---------------------------------------------------------------------------
// signed logsumexp over the 4 pfaffians per batch element
// ---------------------------------------------------------------------------
__global__ void combine_kernel(float* __restrict__ out) {
    int b = threadIdx.x;
    if (b < BATCH) {
        float la[NPFS], sg[NPFS];
        float mx = -INFINITY;
        #pragma unroll
        for (int p = 0; p < NPFS; p++) {
            la[p] = g_logabs[b * NPFS + p];
            sg[p] = g_sign[b * NPFS + p];
            mx = fmaxf(mx, la[p]);
        }
        float val = 0.f;
        #pragma unroll
        for (int p = 0; p < NPFS; p++)
            val += sg[p] * expf(la[p] - mx);
        out[b]         = (val > 0.f) ? 1.f : ((val < 0.f) ? -1.f : 0.f);
        out[BATCH + b] = mx + logf(fabsf(val));
    }
}

// ---------------------------------------------------------------------------
extern "C" void kernel_launch(void* const* d_in, const int* in_sizes, int n_in,
                              void* d_out, int out_size) {
    const float* F   = (const float*)d_in[0];   // (4, 512, 512) fp32
    const int*   idx = (const int*)  d_in[1];   // (128, 256) int32
    float*       out = (float*)d_out;           // (2, 128) fp32

    const size_t shmem = (size_t)(L_ELEMS + 11 * NP) * sizeof(float); // ~144.5 KB
    cudaFuncSetAttribute(pf_kernel, cudaFuncAttributeMaxDynamicSharedMemorySize,
                         (int)shmem);

    pf_kernel<<<NMAT, NTHR, shmem>>>(F, idx);
    combine_kernel<<<1, 128>>>(out);
}

// round 13
// speedup vs baseline: 1.0003x; 1.0003x over previous
#include <cuda_runtime.h>
#include <math.h>

#define NPFS  4
#define NF    512
#define NP    256
#define BATCH 128
#define NMAT  (BATCH * NPFS)            // 512 matrices
#define NTHR  1024
#define NW    (NTHR / 32)               // 32 warps

// padded, 16B-aligned row bases for the lower triangle
__device__ __host__ __forceinline__ unsigned rowb(int r) {
    return ((unsigned)((r * (r - 1)) / 2 + 6 * r)) & ~3u;
}
#define L_ELEMS 34176                    // >= rowb(255) + 260, mult of 4

// Scratch (__device__ globals — allocations forbidden)
__device__ float g_sign[NMAT];
__device__ float g_logabs[NMAT];

// reduce (absmax, signed value, lowest index on ties) within a warp
__device__ __forceinline__ void wred3(float& bv, float& sv, int& bi) {
    #pragma unroll
    for (int off = 16; off; off >>= 1) {
        float ov = __shfl_down_sync(0xffffffffu, bv, off);
        float os = __shfl_down_sync(0xffffffffu, sv, off);
        int   oi = __shfl_down_sync(0xffffffffu, bi, off);
        if (ov > bv || (ov == bv && oi < bi)) { bv = ov; sv = os; bi = oi; }
    }
}

// ---------------------------------------------------------------------------
// Kernel: one CTA per matrix. Lower triangle (padded rows) in smem.
// Parlett-Reid with partial pivoting, TWO steps fused into ONE rank-4 pass.
// 3 barriers per double-step. Column caches are split into X (colA/colB:
// read-only in phase BC, written by phase E / gather) and Y (colAn/colBn/
// colBr: written by BC, read by D) so no scalar is read and written in the
// same phase. Dead swap writes (row kp1 cols<=k3; whole col kp1 if kp1<=k3)
// are skipped, making the remaining raw reads race-free.
// ---------------------------------------------------------------------------
__global__ __launch_bounds__(NTHR, 1)
void pf_kernel(const float* __restrict__ F, const int* __restrict__ idx) {
    extern __shared__ float sm[];
    float* L     = sm;                  // [L_ELEMS]
    float* tau1  = sm + L_ELEMS;        // [NP]
    float* v1    = tau1 + NP;           // [NP]
    float* tau2  = v1 + NP;             // [NP]
    float* v2    = tau2 + NP;           // [NP]
    float* tau1p = v2 + NP;             // [NP]  swap-b-permuted tau1
    float* v1p   = tau1p + NP;          // [NP]
    float* colA  = v1p + NP;            // [NP]  X: column k   at step start
    float* colB  = colA + NP;           // [NP]  X: column k+1 at step start
    float* colAn = colB + NP;           // [NP]  Y: updated column k+2
    float* colBn = colAn + NP;          // [NP]  Y: updated column k+3
    float* colBr = colBn + NP;          // [NP]  Y: raw column k+3 (pre-update-1)

    __shared__ int   s_idx[NP];
    __shared__ float s_rv[NW];
    __shared__ float s_sv[NW];
    __shared__ int   s_ri[NW];

    const int tid  = threadIdx.x;
    const int lane = tid & 31;
    const int wid  = tid >> 5;
    const int m    = blockIdx.x;
    const int b    = m >> 2;
    const int p    = m & 3;

    if (tid < NP) s_idx[tid] = idx[b * NP + tid];
    __syncthreads();

    // ---- gather (warp per row), antisym fused, + X col cache + pivot scan ----
    {
        float bv = -1.f, sv = 0.f; int bi = NP;
        const float* Fp = F + ((size_t)p << 18);
        for (int r = wid; r < NP; r += NW) {
            const int ir = s_idx[r];
            const float* rowp = Fp + ((size_t)ir << 9);
            unsigned base = rowb(r);
            for (int c = lane; c < r; c += 32) {
                const int ic = s_idx[c];
                float val = 0.5f * (__ldg(&rowp[ic]) - __ldg(&Fp[((size_t)ic << 9) + ir]));
                L[base + c] = val;
                if (c == 0) {
                    colA[r] = val;
                    float a = fabsf(val);
                    if (a > bv || (a == bv && r < bi)) { bv = a; sv = val; bi = r; }
                }
                if (c == 1) colB[r] = val;
            }
        }
        wred3(bv, sv, bi);
        if (lane == 0) { s_rv[wid] = bv; s_sv[wid] = sv; s_ri[wid] = bi; }
    }
    __syncthreads();

    float sign = 1.f, logabs = 0.f;   // live in thread 0

    for (int k = 0; k < NP; k += 4) {
        const int p1 = k + 1;
        const int k2 = k + 2;
        const int k3 = k + 3;
        const int k4 = k + 4;
        const int k5 = k + 5;

        // ---- phase A: reduce pivot-a candidates (butterfly over NW) ----
        float pv = s_rv[lane & (NW - 1)];
        float ps = s_sv[lane & (NW - 1)];
        int   pi = s_ri[lane & (NW - 1)];
        #pragma unroll
        for (int off = NW / 2; off; off >>= 1) {
            float ov = __shfl_xor_sync(0xffffffffu, pv, off);
            float os = __shfl_xor_sync(0xffffffffu, ps, off);
            int   oi = __shfl_xor_sync(0xffffffffu, pi, off);
            if (ov > pv || (ov == pv && oi < pi)) { pv = ov; ps = os; pi = oi; }
        }
        const int   kp1  = pi;                 // pivot-a row in (k, NP)
        const float piv1 = -ps;                // post-swap A[k][k+1] = -colA[kp1]
        if (tid == 0) {
            if (kp1 != p1)  sign = -sign;
            if (piv1 < 0.f) sign = -sign;
            logabs += logf(fabsf(piv1));
        }

        // ---- phase BC (merged): tau1/v1 + live swap-a (dead writes skipped)
        //      + updated columns k2,k3 into Y + pivot-b scan ----
        {
            float bv = -1.f, sv = 0.f; int bi = NP;
            if (tid >= k2 && tid < NP) {
                const int t = tid;
                const float rp = 1.0f / piv1;
                const float ta = (t == kp1 ? colA[p1] : colA[t]) * rp;
                const bool kp1_low = (kp1 <= k3);   // col kp1 dead after BC
                float vv;
                if (kp1 != p1) {
                    if (t < kp1) {
                        vv = -L[rowb(kp1) + t];
                        if (t > k3) L[rowb(kp1) + t] = -colB[t];  // skip dead cols k2,k3
                    } else if (t == kp1) {
                        vv = -colB[kp1];
                    } else {
                        vv = L[rowb(t) + kp1];
                        if (!kp1_low) L[rowb(t) + kp1] = colB[t]; // skip dead col kp1
                    }
                } else {
                    vv = colB[t];
                }
                tau1[t] = ta;
                v1[t]   = vv;

                if (t >= k3) {
                    // cross-thread scalars recomputed locally from X/L (race-free)
                    const float t1k2 = (k2 == kp1 ? colA[p1] : colA[k2]) * rp;
                    const float t1k3 = (k3 == kp1 ? colA[p1] : colA[k3]) * rp;
                    float v1k2, v1k3;
                    if (kp1 == p1) {
                        v1k2 = colB[k2];
                        v1k3 = colB[k3];
                    } else {
                        v1k2 = (kp1 > k2) ? -L[rowb(kp1) + k2] : -colB[kp1];
                        v1k3 = (kp1 > k3) ? -L[rowb(kp1) + k3]
                             : (kp1 == k3) ? -colB[kp1]
                             : L[rowb(k3) + k2];               // kp1 == k2
                    }
                    float rawx, rawy;   // A_a[t][k2], A_a[t][k3]
                    if (t == kp1) {
                        rawx = -colB[k2];
                        rawy = -colB[k3];
                    } else {
                        float2 rw = *(const float2*)&L[rowb(t) + k2];
                        rawx = (kp1 == k2) ? colB[t] : rw.x;   // skipped write value
                        rawy = (kp1 == k3) ? colB[t] : rw.y;
                    }
                    const float ca = rawx + vv * t1k2 - ta * v1k2;   // A'[t][k2]
                    const float cb = rawy + vv * t1k3 - ta * v1k3;   // A'[t][k3]
                    colAn[t] = ca;
                    colBn[t] = cb;
                    colBr[t] = rawy;
                    bv = fabsf(ca); sv = ca; bi = t;
                }
            }
            wred3(bv, sv, bi);
            if (lane == 0) { s_rv[wid] = bv; s_sv[wid] = sv; s_ri[wid] = bi; }
        }
        __syncthreads();

        // ---- phase D: pivot-b reduce; tau2/v2 fill + swap-b (raw writes);
        //      permuted tau1p/v1p ----
        pv = s_rv[lane & (NW - 1)];
        ps = s_sv[lane & (NW - 1)];
        pi = s_ri[lane & (NW - 1)];
        #pragma unroll
        for (int off = NW / 2; off; off >>= 1) {
            float ov = __shfl_xor_sync(0xffffffffu, pv, off);
            float os = __shfl_xor_sync(0xffffffffu, ps, off);
            int   oi = __shfl_xor_sync(0xffffffffu, pi, off);
            if (ov > pv || (ov == pv && oi < pi)) { pv = ov; ps = os; pi = oi; }
        }
        const int   kp2  = pi;                 // pivot-b row in (k2, NP)
        const float piv2 = -ps;                // post-swap A'[k2][k3] = -colAn[kp2]
        if (tid == 0) {
            if (kp2 != k3)  sign = -sign;
            if (piv2 < 0.f) sign = -sign;
            logabs += logf(fabsf(piv2));
        }
        if (tid >= k4 && tid < NP) {
            const int t = tid;
            const float rp2 = 1.0f / piv2;
            const float ta = (t == kp2 ? colAn[k3] : colAn[t]) * rp2;
            float vv;
            if (kp2 != k3) {
                if (t < kp2) {
                    vv = -(L[rowb(kp2) + t] + v1[kp2] * tau1[t] - tau1[kp2] * v1[t]);
                    L[rowb(kp2) + t] = -colBr[t];            // raw swap write
                } else if (t == kp2) {
                    vv = -colBn[kp2];                        // -A'[kp2][k3]
                } else {
                    vv = L[rowb(t) + kp2] + v1[t] * tau1[kp2] - tau1[t] * v1[kp2];
                    L[rowb(t) + kp2] = colBr[t];             // raw swap write
                }
            } else {
                vv = colBn[t];
            }
            tau2[t] = ta;
            v2[t]   = vv;
            tau1p[t] = (t == kp2) ? tau1[k3] : tau1[t];      // P-permuted step-1 vectors
            v1p[t]   = (t == kp2) ? v1[k3]   : v1[t];
        }
        __syncthreads();

        // ---- phase E: ONE rank-4 trailing pass, 4 rows per warp;
        //      extraction writes X (cols k4,k5) for the next double-step ----
        if (k4 < NP) {
            float bv = -1.f, sv = 0.f; int bi = NP;
            const int cstart = k4;   // k % 4 == 0 -> 16B aligned
            for (int pr = wid; ; pr += 2 * NW) {
                const int r0 = k5 + 2 * pr;
                if (r0 >= NP) break;
                const int r1 = r0 + 1;
                const int r2 = r0 + 2 * NW;
                const int r3 = r2 + 1;
                const bool ok1 = r1 < NP, ok2 = r2 < NP, ok3 = r3 < NP;

                const unsigned b0 = rowb(r0);
                const unsigned b1 = ok1 ? rowb(r1) : 0u;
                const unsigned b2 = ok2 ? rowb(r2) : 0u;
                const unsigned b3 = ok3 ? rowb(r3) : 0u;
                const int e0 = (r0 + 3) & ~3;
                const int e1 = ok1 ? ((r1 + 3) & ~3) : 0;
                const int e2 = ok2 ? ((r2 + 3) & ~3) : 0;
                const int e3 = ok3 ? ((r3 + 3) & ~3) : 0;
                int emax = e0;
                if (e1 > emax) emax = e1;
                if (e2 > emax) emax = e2;
                if (e3 > emax) emax = e3;

                const float t0 = tau1p[r0], w0 = v1p[r0];
                const float u0 = tau2[r0],  z0 = v2[r0];
                const float t1r = ok1 ? tau1p[r1] : 0.f, w1r = ok1 ? v1p[r1] : 0.f;
                const float u1r = ok1 ? tau2[r1]  : 0.f, z1r = ok1 ? v2[r1]  : 0.f;
                const float t2r = ok2 ? tau1p[r2] : 0.f, w2r = ok2 ? v1p[r2] : 0.f;
                const float u2r = ok2 ? tau2[r2]  : 0.f, z2r = ok2 ? v2[r2]  : 0.f;
                const float t3r = ok3 ? tau1p[r3] : 0.f, w3r = ok3 ? v1p[r3] : 0.f;
                const float u3r = ok3 ? tau2[r3]  : 0.f, z3r = ok3 ? v2[r3]  : 0.f;

                for (int cc = cstart + 4 * lane; cc < emax; cc += 128) {
                    const float4 t1c = *(const float4*)&tau1p[cc];
                    const float4 w1c = *(const float4*)&v1p[cc];
                    const float4 t2c = *(const float4*)&tau2[cc];
                    const float4 w2c = *(const float4*)&v2[cc];

                    #define ROW_UPD(BX, EX, TR, WR, UR, ZR, RX)                          \
                    if (cc < EX) {                                                       \
                        float4 x = *(const float4*)&L[BX + cc];                          \
                        x.x += WR * t1c.x - TR * w1c.x + ZR * t2c.x - UR * w2c.x;        \
                        x.y += WR * t1c.y - TR * w1c.y + ZR * t2c.y - UR * w2c.y;        \
                        x.z += WR * t1c.z - TR * w1c.z + ZR * t2c.z - UR * w2c.z;        \
                        x.w += WR * t1c.w - TR * w1c.w + ZR * t2c.w - UR * w2c.w;        \
                        *(float4*)&L[BX + cc] = x;                                       \
                        if (cc == cstart) {                                              \
                            colA[RX] = x.x; colB[RX] = x.y;                              \
                            float a_ = fabsf(x.x);                                       \
                            if (a_ > bv || (a_ == bv && (RX) < bi)) {                    \
                                bv = a_; sv = x.x; bi = RX;                              \
                            }                                                            \
                        }                                                                \
                    }

                    ROW_UPD(b0, e0, t0,  w0,  u0,  z0,  r0)
                    ROW_UPD(b1, e1, t1r, w1r, u1r, z1r, r1)
                    ROW_UPD(b2, e2, t2r, w2r, u2r, z2r, r2)
                    ROW_UPD(b3, e3, t3r, w3r, u3r, z3r, r3)
                    #undef ROW_UPD
                }
            }
            wred3(bv, sv, bi);
            if (lane == 0) { s_rv[wid] = bv; s_sv[wid] = sv; s_ri[wid] = bi; }
        }
        __syncthreads();
    }

    if (tid == 0) { g_sign[m] = sign; g_logabs[m] = logabs; }
}

// ---------------------------------------------------------------------------
// signed logsumexp over the 4 pfaffians per batch element
// ---------------------------------------------------------------------------
__global__ void combine_kernel(float* __restrict__ out) {
    int b = threadIdx.x;
    if (b < BATCH) {
        float la[NPFS], sg[NPFS];
        float mx = -INFINITY;
        #pragma unroll
        for (int p = 0; p < NPFS; p++) {
            la[p] = g_logabs[b * NPFS + p];
            sg[p] = g_sign[b * NPFS + p];
            mx = fmaxf(mx, la[p]);
        }
        float val = 0.f;
        #pragma unroll
        for (int p = 0; p < NPFS; p++)
            val += sg[p] * expf(la[p] - mx);
        out[b]         = (val > 0.f) ? 1.f : ((val < 0.f) ? -1.f : 0.f);
        out[BATCH + b] = mx + logf(fabsf(val));
    }
}

// ---------------------------------------------------------------------------
extern "C" void kernel_launch(void* const* d_in, const int* in_sizes, int n_in,
                              void* d_out, int out_size) {
    const float* F   = (const float*)d_in[0];   // (4, 512, 512) fp32
    const int*   idx = (const int*)  d_in[1];   // (128, 256) int32
    float*       out = (float*)d_out;           // (2, 128) fp32

    const size_t shmem = (size_t)(L_ELEMS + 11 * NP) * sizeof(float); // ~144.5 KB
    cudaFuncSetAttribute(pf_kernel, cudaFuncAttributeMaxDynamicSharedMemorySize,
                         (int)shmem);

    pf_kernel<<<NMAT, NTHR, shmem>>>(F, idx);
    combine_kernel<<<1, 128>>>(out);
}

// round 14
// speedup vs baseline: 1.0006x; 1.0003x over previous
#include <cuda_runtime.h>
#include <math.h>

#define NPFS  4
#define NF    512
#define NP    256
#define BATCH 128
#define NMAT  (BATCH * NPFS)            // 512 matrices
#define NTHR  1024
#define NW    (NTHR / 32)               // 32 warps

// padded, 16B-aligned row bases for the lower triangle
__device__ __host__ __forceinline__ unsigned rowb(int r) {
    return ((unsigned)((r * (r - 1)) / 2 + 6 * r)) & ~3u;
}
#define L_ELEMS 34176                    // >= rowb(255) + 260, mult of 4

// Scratch (__device__ globals — allocations forbidden)
__device__ float g_sign[NMAT];
__device__ float g_logabs[NMAT];

// reduce (absmax, signed value, lowest index on ties) within a warp
__device__ __forceinline__ void wred3(float& bv, float& sv, int& bi) {
    #pragma unroll
    for (int off = 16; off; off >>= 1) {
        float ov = __shfl_down_sync(0xffffffffu, bv, off);
        float os = __shfl_down_sync(0xffffffffu, sv, off);
        int   oi = __shfl_down_sync(0xffffffffu, bi, off);
        if (ov > bv || (ov == bv && oi < bi)) { bv = ov; sv = os; bi = oi; }
    }
}

// ---------------------------------------------------------------------------
// Kernel: one CTA per matrix. Lower triangle (padded rows) in smem.
// Parlett-Reid with partial pivoting, TWO steps fused into ONE rank-4 pass.
// 3 barriers per double-step. Column caches are split into X (colA/colB:
// read-only in phase BC, written by phase E / gather) and Y (colAn/colBn/
// colBr: written by BC, read by D) so no scalar is read and written in the
// same phase. Dead swap writes (row kp1 cols<=k3; whole col kp1 if kp1<=k3)
// are skipped, making the remaining raw reads race-free.
// ---------------------------------------------------------------------------
__global__ __launch_bounds__(NTHR, 1)
void pf_kernel(const float* __restrict__ F, const int* __restrict__ idx) {
    extern __shared__ float sm[];
    float* L     = sm;                  // [L_ELEMS]
    float* tau1  = sm + L_ELEMS;        // [NP]
    float* v1    = tau1 + NP;           // [NP]
    float* tau2  = v1 + NP;             // [NP]
    float* v2    = tau2 + NP;           // [NP]
    float* tau1p = v2 + NP;             // [NP]  swap-b-permuted tau1
    float* v1p   = tau1p + NP;          // [NP]
    float* colA  = v1p + NP;            // [NP]  X: column k   at step start
    float* colB  = colA + NP;           // [NP]  X: column k+1 at step start
    float* colAn = colB + NP;           // [NP]  Y: updated column k+2
    float* colBn = colAn + NP;          // [NP]  Y: updated column k+3
    float* colBr = colBn + NP;          // [NP]  Y: raw column k+3 (pre-update-1)

    __shared__ int   s_idx[NP];
    __shared__ float s_rv[NW];
    __shared__ float s_sv[NW];
    __shared__ int   s_ri[NW];

    const int tid  = threadIdx.x;
    const int lane = tid & 31;
    const int wid  = tid >> 5;
    const int m    = blockIdx.x;
    const int b    = m >> 2;
    const int p    = m & 3;

    if (tid < NP) s_idx[tid] = idx[b * NP + tid];
    __syncthreads();

    // ---- gather (warp per row), antisym fused, + X col cache + pivot scan ----
    {
        float bv = -1.f, sv = 0.f; int bi = NP;
        const float* Fp = F + ((size_t)p << 18);
        for (int r = wid; r < NP; r += NW) {
            const int ir = s_idx[r];
            const float* rowp = Fp + ((size_t)ir << 9);
            unsigned base = rowb(r);
            for (int c = lane; c < r; c += 32) {
                const int ic = s_idx[c];
                float val = 0.5f * (__ldg(&rowp[ic]) - __ldg(&Fp[((size_t)ic << 9) + ir]));
                L[base + c] = val;
                if (c == 0) {
                    colA[r] = val;
                    float a = fabsf(val);
                    if (a > bv || (a == bv && r < bi)) { bv = a; sv = val; bi = r; }
                }
                if (c == 1) colB[r] = val;
            }
        }
        wred3(bv, sv, bi);
        if (lane == 0) { s_rv[wid] = bv; s_sv[wid] = sv; s_ri[wid] = bi; }
    }
    __syncthreads();

    float sign = 1.f, logabs = 0.f;   // live in thread 0

    for (int k = 0; k < NP; k += 4) {
        const int p1 = k + 1;
        const int k2 = k + 2;
        const int k3 = k + 3;
        const int k4 = k + 4;
        const int k5 = k + 5;

        // ---- phase A: reduce pivot-a candidates (butterfly over NW) ----
        float pv = s_rv[lane & (NW - 1)];
        float ps = s_sv[lane & (NW - 1)];
        int   pi = s_ri[lane & (NW - 1)];
        #pragma unroll
        for (int off = NW / 2; off; off >>= 1) {
            float ov = __shfl_xor_sync(0xffffffffu, pv, off);
            float os = __shfl_xor_sync(0xffffffffu, ps, off);
            int   oi = __shfl_xor_sync(0xffffffffu, pi, off);
            if (ov > pv || (ov == pv && oi < pi)) { pv = ov; ps = os; pi = oi; }
        }
        const int   kp1  = pi;                 // pivot-a row in (k, NP)
        const float piv1 = -ps;                // post-swap A[k][k+1] = -colA[kp1]
        if (tid == 0) {
            if (kp1 != p1)  sign = -sign;
            if (piv1 < 0.f) sign = -sign;
            logabs += logf(fabsf(piv1));
        }

        // ---- phase BC (merged): tau1/v1 + live swap-a (dead writes skipped)
        //      + updated columns k2,k3 into Y + pivot-b scan ----
        {
            float bv = -1.f, sv = 0.f; int bi = NP;
            if (tid >= k2 && tid < NP) {
                const int t = tid;
                const float rp = 1.0f / piv1;
                const float ta = (t == kp1 ? colA[p1] : colA[t]) * rp;
                const bool kp1_low = (kp1 <= k3);   // col kp1 dead after BC
                float vv;
                if (kp1 != p1) {
                    if (t < kp1) {
                        vv = -L[rowb(kp1) + t];
                        if (t > k3) L[rowb(kp1) + t] = -colB[t];  // skip dead cols k2,k3
                    } else if (t == kp1) {
                        vv = -colB[kp1];
                    } else {
                        vv = L[rowb(t) + kp1];
                        if (!kp1_low) L[rowb(t) + kp1] = colB[t]; // skip dead col kp1
                    }
                } else {
                    vv = colB[t];
                }
                tau1[t] = ta;
                v1[t]   = vv;

                if (t >= k3) {
                    // cross-thread scalars recomputed locally from X/L (race-free)
                    const float t1k2 = (k2 == kp1 ? colA[p1] : colA[k2]) * rp;
                    const float t1k3 = (k3 == kp1 ? colA[p1] : colA[k3]) * rp;
                    float v1k2, v1k3;
                    if (kp1 == p1) {
                        v1k2 = colB[k2];
                        v1k3 = colB[k3];
                    } else {
                        v1k2 = (kp1 > k2) ? -L[rowb(kp1) + k2] : -colB[kp1];
                        v1k3 = (kp1 > k3) ? -L[rowb(kp1) + k3]
                             : (kp1 == k3) ? -colB[kp1]
                             : L[rowb(k3) + k2];               // kp1 == k2
                    }
                    float rawx, rawy;   // A_a[t][k2], A_a[t][k3]
                    if (t == kp1) {
                        rawx = -colB[k2];
                        rawy = -colB[k3];
                    } else {
                        float2 rw = *(const float2*)&L[rowb(t) + k2];
                        rawx = (kp1 == k2) ? colB[t] : rw.x;   // skipped write value
                        rawy = (kp1 == k3) ? colB[t] : rw.y;
                    }
                    const float ca = rawx + vv * t1k2 - ta * v1k2;   // A'[t][k2]
                    const float cb = rawy + vv * t1k3 - ta * v1k3;   // A'[t][k3]
                    colAn[t] = ca;
                    colBn[t] = cb;
                    colBr[t] = rawy;
                    bv = fabsf(ca); sv = ca; bi = t;
                }
            }
            wred3(bv, sv, bi);
            if (lane == 0) { s_rv[wid] = bv; s_sv[wid] = sv; s_ri[wid] = bi; }
        }
        __syncthreads();

        // ---- phase D: pivot-b reduce; tau2/v2 fill + swap-b (raw writes);
        //      permuted tau1p/v1p ----
        pv = s_rv[lane & (NW - 1)];
        ps = s_sv[lane & (NW - 1)];
        pi = s_ri[lane & (NW - 1)];
        #pragma unroll
        for (int off = NW / 2; off; off >>= 1) {
            float ov = __shfl_xor_sync(0xffffffffu, pv, off);
            float os = __shfl_xor_sync(0xffffffffu, ps, off);
            int   oi = __shfl_xor_sync(0xffffffffu, pi, off);
            if (ov > pv || (ov == pv && oi < pi)) { pv = ov; ps = os; pi = oi; }
        }
        const int   kp2  = pi;                 // pivot-b row in (k2, NP)
        const float piv2 = -ps;                // post-swap A'[k2][k3] = -colAn[kp2]
        if (tid == 0) {
            if (kp2 != k3)  sign = -sign;
            if (piv2 < 0.f) sign = -sign;
            logabs += logf(fabsf(piv2));
        }
        if (tid >= k4 && tid < NP) {
            const int t = tid;
            const float rp2 = 1.0f / piv2;
            const float ta = (t == kp2 ? colAn[k3] : colAn[t]) * rp2;
            float vv;
            if (kp2 != k3) {
                if (t < kp2) {
                    vv = -(L[rowb(kp2) + t] + v1[kp2] * tau1[t] - tau1[kp2] * v1[t]);
                    L[rowb(kp2) + t] = -colBr[t];            // raw swap write
                } else if (t == kp2) {
                    vv = -colBn[kp2];                        // -A'[kp2][k3]
                } else {
                    vv = L[rowb(t) + kp2] + v1[t] * tau1[kp2] - tau1[t] * v1[kp2];
                    L[rowb(t) + kp2] = colBr[t];             // raw swap write
                }
            } else {
                vv = colBn[t];
            }
            tau2[t] = ta;
            v2[t]   = vv;
            tau1p[t] = (t == kp2) ? tau1[k3] : tau1[t];      // P-permuted step-1 vectors
            v1p[t]   = (t == kp2) ? v1[k3]   : v1[t];
        }
        __syncthreads();

        // ---- phase E: ONE rank-4 trailing pass, 4 rows per warp;
        //      extraction writes X (cols k4,k5) for the next double-step ----
        if (k4 < NP) {
            float bv = -1.f, sv = 0.f; int bi = NP;
            const int cstart = k4;   // k % 4 == 0 -> 16B aligned
            for (int pr = wid; ; pr += 2 * NW) {
                const int r0 = k5 + 2 * pr;
                if (r0 >= NP) break;
                const int r1 = r0 + 1;
                const int r2 = r0 + 2 * NW;
                const int r3 = r2 + 1;
                const bool ok1 = r1 < NP, ok2 = r2 < NP, ok3 = r3 < NP;

                const unsigned b0 = rowb(r0);
                const unsigned b1 = ok1 ? rowb(r1) : 0u;
                const unsigned b2 = ok2 ? rowb(r2) : 0u;
                const unsigned b3 = ok3 ? rowb(r3) : 0u;
                const int e0 = (r0 + 3) & ~3;
                const int e1 = ok1 ? ((r1 + 3) & ~3) : 0;
                const int e2 = ok2 ? ((r2 + 3) & ~3) : 0;
                const int e3 = ok3 ? ((r3 + 3) & ~3) : 0;
                int emax = e0;
                if (e1 > emax) emax = e1;
                if (e2 > emax) emax = e2;
                if (e3 > emax) emax = e3;

                const float t0 = tau1p[r0], w0 = v1p[r0];
                const float u0 = tau2[r0],  z0 = v2[r0];
                const float t1r = ok1 ? tau1p[r1] : 0.f, w1r = ok1 ? v1p[r1] : 0.f;
                const float u1r = ok1 ? tau2[r1]  : 0.f, z1r = ok1 ? v2[r1]  : 0.f;
                const float t2r = ok2 ? tau1p[r2] : 0.f, w2r = ok2 ? v1p[r2] : 0.f;
                const float u2r = ok2 ? tau2[r2]  : 0.f, z2r = ok2 ? v2[r2]  : 0.f;
                const float t3r = ok3 ? tau1p[r3] : 0.f, w3r = ok3 ? v1p[r3] : 0.f;
                const float u3r = ok3 ? tau2[r3]  : 0.f, z3r = ok3 ? v2[r3]  : 0.f;

                for (int cc = cstart + 4 * lane; cc < emax; cc += 128) {
                    const float4 t1c = *(const float4*)&tau1p[cc];
                    const float4 w1c = *(const float4*)&v1p[cc];
                    const float4 t2c = *(const float4*)&tau2[cc];
                    const float4 w2c = *(const float4*)&v2[cc];

                    #define ROW_UPD(BX, EX, TR, WR, UR, ZR, RX)                          \
                    if (cc < EX) {                                                       \
                        float4 x = *(const float4*)&L[BX + cc];                          \
                        x.x += WR * t1c.x - TR * w1c.x + ZR * t2c.x - UR * w2c.x;        \
                        x.y += WR * t1c.y - TR * w1c.y + ZR * t2c.y - UR * w2c.y;        \
                        x.z += WR * t1c.z - TR * w1c.z + ZR * t2c.z - UR * w2c.z;        \
                        x.w += WR * t1c.w - TR * w1c.w + ZR * t2c.w - UR * w2c.w;        \
                        *(float4*)&L[BX + cc] = x;                                       \
                        if (cc == cstart) {                                              \
                            colA[RX] = x.x; colB[RX] = x.y;                              \
                            float a_ = fabsf(x.x);                                       \
                            if (a_ > bv || (a_ == bv && (RX) < bi)) {                    \
                                bv = a_; sv = x.x; bi = RX;                              \
                            }                                                            \
                        }                                                                \
                    }

                    ROW_UPD(b0, e0, t0,  w0,  u0,  z0,  r0)
                    ROW_UPD(b1, e1, t1r, w1r, u1r, z1r, r1)
                    ROW_UPD(b2, e2, t2r, w2r, u2r, z2r, r2)
                    ROW_UPD(b3, e3, t3r, w3r, u3r, z3r, r3)
                    #undef ROW_UPD
                }
            }
            wred3(bv, sv, bi);
            if (lane == 0) { s_rv[wid] = bv; s_sv[wid] = sv; s_ri[wid] = bi; }
        }
        __syncthreads();
    }

    if (tid == 0) { g_sign[m] = sign; g_logabs[m] = logabs; }
}

// ---------------------------------------------------------------------------
// signed logsumexp over the 4 pfaffians per batch element
// ---------------------------------------------------------------------------
__global__ void combine_kernel(float* __restrict__ out) {
    int b = threadIdx.x;
    if (b < BATCH) {
        float la[NPFS], sg[NPFS];
        float mx = -INFINITY;
        #pragma unroll
        for (int p = 0; p < NPFS; p++) {
            la[p] = g_logabs[b * NPFS + p];
            sg[p] = g_sign[b * NPFS + p];
            mx = fmaxf(mx, la[p]);
        }
        float val = 0.f;
        #pragma unroll
        for (int p = 0; p < NPFS; p++)
            val += sg[p] * expf(la[p] - mx);
        out[b]         = (val > 0.f) ? 1.f : ((val < 0.f) ? -1.f : 0.f);
        out[BATCH + b] = mx + logf(fabsf(val));
    }
}

// ---------------------------------------------------------------------------
extern "C" void kernel_launch(void* const* d_in, const int* in_sizes, int n_in,
                              void* d_out, int out_size) {
    const float* F   = (const float*)d_in[0];   // (4, 512, 512) fp32
    const int*   idx = (const int*)  d_in[1];   // (128, 256) int32
    float*       out = (float*)d_out;           // (2, 128) fp32

    const size_t shmem = (size_t)(L_ELEMS + 11 * NP) * sizeof(float); // ~144.5 KB
    cudaFuncSetAttribute(pf_kernel, cudaFuncAttributeMaxDynamicSharedMemorySize,
                         (int)shmem);

    pf_kernel<<<NMAT, NTHR, shmem>>>(F, idx);
    combine_kernel<<<1, 128>>>(out);
}

// round 15
// speedup vs baseline: 1.0010x; 1.0004x over previous
#include <cuda_runtime.h>
#include <math.h>

#define NPFS  4
#define NF    512
#define NP    256
#define BATCH 128
#define NMAT  (BATCH * NPFS)            // 512 matrices
#define NTHR  1024
#define NW    (NTHR / 32)               // 32 warps

// padded, 16B-aligned row bases for the lower triangle
__device__ __host__ __forceinline__ unsigned rowb(int r) {
    return ((unsigned)((r * (r - 1)) / 2 + 6 * r)) & ~3u;
}
#define L_ELEMS 34176                    // >= rowb(255) + 260, mult of 4

// Scratch (__device__ globals — allocations forbidden)
__device__ float g_sign[NMAT];
__device__ float g_logabs[NMAT];

// reduce (absmax, signed value, lowest index on ties) within a warp
__device__ __forceinline__ void wred3(float& bv, float& sv, int& bi) {
    #pragma unroll
    for (int off = 16; off; off >>= 1) {
        float ov = __shfl_down_sync(0xffffffffu, bv, off);
        float os = __shfl_down_sync(0xffffffffu, sv, off);
        int   oi = __shfl_down_sync(0xffffffffu, bi, off);
        if (ov > bv || (ov == bv && oi < bi)) { bv = ov; sv = os; bi = oi; }
    }
}

// ---------------------------------------------------------------------------
// Kernel: one CTA per matrix. Lower triangle (padded rows) in smem.
// Parlett-Reid with partial pivoting, TWO steps fused into ONE rank-4 pass.
// 3 barriers per double-step. Column caches are split into X (colA/colB:
// read-only in phase BC, written by phase E / gather) and Y (colAn/colBn/
// colBr: written by BC, read by D) so no scalar is read and written in the
// same phase. Dead swap writes (row kp1 cols<=k3; whole col kp1 if kp1<=k3)
// are skipped, making the remaining raw reads race-free.
// ---------------------------------------------------------------------------
__global__ __launch_bounds__(NTHR, 1)
void pf_kernel(const float* __restrict__ F, const int* __restrict__ idx) {
    extern __shared__ float sm[];
    float* L     = sm;                  // [L_ELEMS]
    float* tau1  = sm + L_ELEMS;        // [NP]
    float* v1    = tau1 + NP;           // [NP]
    float* tau2  = v1 + NP;             // [NP]
    float* v2    = tau2 + NP;           // [NP]
    float* tau1p = v2 + NP;             // [NP]  swap-b-permuted tau1
    float* v1p   = tau1p + NP;          // [NP]
    float* colA  = v1p + NP;            // [NP]  X: column k   at step start
    float* colB  = colA + NP;           // [NP]  X: column k+1 at step start
    float* colAn = colB + NP;           // [NP]  Y: updated column k+2
    float* colBn = colAn + NP;          // [NP]  Y: updated column k+3
    float* colBr = colBn + NP;          // [NP]  Y: raw column k+3 (pre-update-1)

    __shared__ int   s_idx[NP];
    __shared__ float s_rv[NW];
    __shared__ float s_sv[NW];
    __shared__ int   s_ri[NW];

    const int tid  = threadIdx.x;
    const int lane = tid & 31;
    const int wid  = tid >> 5;
    const int m    = blockIdx.x;
    const int b    = m >> 2;
    const int p    = m & 3;

    if (tid < NP) s_idx[tid] = idx[b * NP + tid];
    __syncthreads();

    // ---- gather (warp per row), antisym fused, + X col cache + pivot scan ----
    {
        float bv = -1.f, sv = 0.f; int bi = NP;
        const float* Fp = F + ((size_t)p << 18);
        for (int r = wid; r < NP; r += NW) {
            const int ir = s_idx[r];
            const float* rowp = Fp + ((size_t)ir << 9);
            unsigned base = rowb(r);
            for (int c = lane; c < r; c += 32) {
                const int ic = s_idx[c];
                float val = 0.5f * (__ldg(&rowp[ic]) - __ldg(&Fp[((size_t)ic << 9) + ir]));
                L[base + c] = val;
                if (c == 0) {
                    colA[r] = val;
                    float a = fabsf(val);
                    if (a > bv || (a == bv && r < bi)) { bv = a; sv = val; bi = r; }
                }
                if (c == 1) colB[r] = val;
            }
        }
        wred3(bv, sv, bi);
        if (lane == 0) { s_rv[wid] = bv; s_sv[wid] = sv; s_ri[wid] = bi; }
    }
    __syncthreads();

    float sign = 1.f, logabs = 0.f;   // live in thread 0

    for (int k = 0; k < NP; k += 4) {
        const int p1 = k + 1;
        const int k2 = k + 2;
        const int k3 = k + 3;
        const int k4 = k + 4;
        const int k5 = k + 5;

        // ---- phase A: reduce pivot-a candidates (butterfly over NW) ----
        float pv = s_rv[lane & (NW - 1)];
        float ps = s_sv[lane & (NW - 1)];
        int   pi = s_ri[lane & (NW - 1)];
        #pragma unroll
        for (int off = NW / 2; off; off >>= 1) {
            float ov = __shfl_xor_sync(0xffffffffu, pv, off);
            float os = __shfl_xor_sync(0xffffffffu, ps, off);
            int   oi = __shfl_xor_sync(0xffffffffu, pi, off);
            if (ov > pv || (ov == pv && oi < pi)) { pv = ov; ps = os; pi = oi; }
        }
        const int   kp1  = pi;                 // pivot-a row in (k, NP)
        const float piv1 = -ps;                // post-swap A[k][k+1] = -colA[kp1]
        if (tid == 0) {
            if (kp1 != p1)  sign = -sign;
            if (piv1 < 0.f) sign = -sign;
            logabs += logf(fabsf(piv1));
        }

        // ---- phase BC (merged): tau1/v1 + live swap-a (dead writes skipped)
        //      + updated columns k2,k3 into Y + pivot-b scan ----
        {
            float bv = -1.f, sv = 0.f; int bi = NP;
            if (tid >= k2 && tid < NP) {
                const int t = tid;
                const float rp = 1.0f / piv1;
                const float ta = (t == kp1 ? colA[p1] : colA[t]) * rp;
                const bool kp1_low = (kp1 <= k3);   // col kp1 dead after BC
                float vv;
                if (kp1 != p1) {
                    if (t < kp1) {
                        vv = -L[rowb(kp1) + t];
                        if (t > k3) L[rowb(kp1) + t] = -colB[t];  // skip dead cols k2,k3
                    } else if (t == kp1) {
                        vv = -colB[kp1];
                    } else {
                        vv = L[rowb(t) + kp1];
                        if (!kp1_low) L[rowb(t) + kp1] = colB[t]; // skip dead col kp1
                    }
                } else {
                    vv = colB[t];
                }
                tau1[t] = ta;
                v1[t]   = vv;

                if (t >= k3) {
                    // cross-thread scalars recomputed locally from X/L (race-free)
                    const float t1k2 = (k2 == kp1 ? colA[p1] : colA[k2]) * rp;
                    const float t1k3 = (k3 == kp1 ? colA[p1] : colA[k3]) * rp;
                    float v1k2, v1k3;
                    if (kp1 == p1) {
                        v1k2 = colB[k2];
                        v1k3 = colB[k3];
                    } else {
                        v1k2 = (kp1 > k2) ? -L[rowb(kp1) + k2] : -colB[kp1];
                        v1k3 = (kp1 > k3) ? -L[rowb(kp1) + k3]
                             : (kp1 == k3) ? -colB[kp1]
                             : L[rowb(k3) + k2];               // kp1 == k2
                    }
                    float rawx, rawy;   // A_a[t][k2], A_a[t][k3]
                    if (t == kp1) {
                        rawx = -colB[k2];
                        rawy = -colB[k3];
                    } else {
                        float2 rw = *(const float2*)&L[rowb(t) + k2];
                        rawx = (kp1 == k2) ? colB[t] : rw.x;   // skipped write value
                        rawy = (kp1 == k3) ? colB[t] : rw.y;
                    }
                    const float ca = rawx + vv * t1k2 - ta * v1k2;   // A'[t][k2]
                    const float cb = rawy + vv * t1k3 - ta * v1k3;   // A'[t][k3]
                    colAn[t] = ca;
                    colBn[t] = cb;
                    colBr[t] = rawy;
                    bv = fabsf(ca); sv = ca; bi = t;
                }
            }
            wred3(bv, sv, bi);
            if (lane == 0) { s_rv[wid] = bv; s_sv[wid] = sv; s_ri[wid] = bi; }
        }
        __syncthreads();

        // ---- phase D: pivot-b reduce; tau2/v2 fill + swap-b (raw writes);
        //      permuted tau1p/v1p ----
        pv = s_rv[lane & (NW - 1)];
        ps = s_sv[lane & (NW - 1)];
        pi = s_ri[lane & (NW - 1)];
        #pragma unroll
        for (int off = NW / 2; off; off >>= 1) {
            float ov = __shfl_xor_sync(0xffffffffu, pv, off);
            float os = __shfl_xor_sync(0xffffffffu, ps, off);
            int   oi = __shfl_xor_sync(0xffffffffu, pi, off);
            if (ov > pv || (ov == pv && oi < pi)) { pv = ov; ps = os; pi = oi; }
        }
        const int   kp2  = pi;                 // pivot-b row in (k2, NP)
        const float piv2 = -ps;                // post-swap A'[k2][k3] = -colAn[kp2]
        if (tid == 0) {
            if (kp2 != k3)  sign = -sign;
            if (piv2 < 0.f) sign = -sign;
            logabs += logf(fabsf(piv2));
        }
        if (tid >= k4 && tid < NP) {
            const int t = tid;
            const float rp2 = 1.0f / piv2;
            const float ta = (t == kp2 ? colAn[k3] : colAn[t]) * rp2;
            float vv;
            if (kp2 != k3) {
                if (t < kp2) {
                    vv = -(L[rowb(kp2) + t] + v1[kp2] * tau1[t] - tau1[kp2] * v1[t]);
                    L[rowb(kp2) + t] = -colBr[t];            // raw swap write
                } else if (t == kp2) {
                    vv = -colBn[kp2];                        // -A'[kp2][k3]
                } else {
                    vv = L[rowb(t) + kp2] + v1[t] * tau1[kp2] - tau1[t] * v1[kp2];
                    L[rowb(t) + kp2] = colBr[t];             // raw swap write
                }
            } else {
                vv = colBn[t];
            }
            tau2[t] = ta;
            v2[t]   = vv;
            tau1p[t] = (t == kp2) ? tau1[k3] : tau1[t];      // P-permuted step-1 vectors
            v1p[t]   = (t == kp2) ? v1[k3]   : v1[t];
        }
        __syncthreads();

        // ---- phase E: ONE rank-4 trailing pass, 4 rows per warp;
        //      extraction writes X (cols k4,k5) for the next double-step ----
        if (k4 < NP) {
            float bv = -1.f, sv = 0.f; int bi = NP;
            const int cstart = k4;   // k % 4 == 0 -> 16B aligned
            for (int pr = wid; ; pr += 2 * NW) {
                const int r0 = k5 + 2 * pr;
                if (r0 >= NP) break;
                const int r1 = r0 + 1;
                const int r2 = r0 + 2 * NW;
                const int r3 = r2 + 1;
                const bool ok1 = r1 < NP, ok2 = r2 < NP, ok3 = r3 < NP;

                const unsigned b0 = rowb(r0);
                const unsigned b1 = ok1 ? rowb(r1) : 0u;
                const unsigned b2 = ok2 ? rowb(r2) : 0u;
                const unsigned b3 = ok3 ? rowb(r3) : 0u;
                const int e0 = (r0 + 3) & ~3;
                const int e1 = ok1 ? ((r1 + 3) & ~3) : 0;
                const int e2 = ok2 ? ((r2 + 3) & ~3) : 0;
                const int e3 = ok3 ? ((r3 + 3) & ~3) : 0;
                int emax = e0;
                if (e1 > emax) emax = e1;
                if (e2 > emax) emax = e2;
                if (e3 > emax) emax = e3;

                const float t0 = tau1p[r0], w0 = v1p[r0];
                const float u0 = tau2[r0],  z0 = v2[r0];
                const float t1r = ok1 ? tau1p[r1] : 0.f, w1r = ok1 ? v1p[r1] : 0.f;
                const float u1r = ok1 ? tau2[r1]  : 0.f, z1r = ok1 ? v2[r1]  : 0.f;
                const float t2r = ok2 ? tau1p[r2] : 0.f, w2r = ok2 ? v1p[r2] : 0.f;
                const float u2r = ok2 ? tau2[r2]  : 0.f, z2r = ok2 ? v2[r2]  : 0.f;
                const float t3r = ok3 ? tau1p[r3] : 0.f, w3r = ok3 ? v1p[r3] : 0.f;
                const float u3r = ok3 ? tau2[r3]  : 0.f, z3r = ok3 ? v2[r3]  : 0.f;

                for (int cc = cstart + 4 * lane; cc < emax; cc += 128) {
                    const float4 t1c = *(const float4*)&tau1p[cc];
                    const float4 w1c = *(const float4*)&v1p[cc];
                    const float4 t2c = *(const float4*)&tau2[cc];
                    const float4 w2c = *(const float4*)&v2[cc];

                    #define ROW_UPD(BX, EX, TR, WR, UR, ZR, RX)                          \
                    if (cc < EX) {                                                       \
                        float4 x = *(const float4*)&L[BX + cc];                          \
                        x.x += WR * t1c.x - TR * w1c.x + ZR * t2c.x - UR * w2c.x;        \
                        x.y += WR * t1c.y - TR * w1c.y + ZR * t2c.y - UR * w2c.y;        \
                        x.z += WR * t1c.z - TR * w1c.z + ZR * t2c.z - UR * w2c.z;        \
                        x.w += WR * t1c.w - TR * w1c.w + ZR * t2c.w - UR * w2c.w;        \
                        *(float4*)&L[BX + cc] = x;                                       \
                        if (cc == cstart) {                                              \
                            colA[RX] = x.x; colB[RX] = x.y;                              \
                            float a_ = fabsf(x.x);                                       \
                            if (a_ > bv || (a_ == bv && (RX) < bi)) {                    \
                                bv = a_; sv = x.x; bi = RX;                              \
                            }                                                            \
                        }                                                                \
                    }

                    ROW_UPD(b0, e0, t0,  w0,  u0,  z0,  r0)
                    ROW_UPD(b1, e1, t1r, w1r, u1r, z1r, r1)
                    ROW_UPD(b2, e2, t2r, w2r, u2r, z2r, r2)
                    ROW_UPD(b3, e3, t3r, w3r, u3r, z3r, r3)
                    #undef ROW_UPD
                }
            }
            wred3(bv, sv, bi);
            if (lane == 0) { s_rv[wid] = bv; s_sv[wid] = sv; s_ri[wid] = bi; }
        }
        __syncthreads();
    }

    if (tid == 0) { g_sign[m] = sign; g_logabs[m] = logabs; }
}

// ---------------------------------------------------------------------------
// signed logsumexp over the 4 pfaffians per batch element
// ---------------------------------------------------------------------------
__global__ void combine_kernel(float* __restrict__ out) {
    int b = threadIdx.x;
    if (b < BATCH) {
        float la[NPFS], sg[NPFS];
        float mx = -INFINITY;
        #pragma unroll
        for (int p = 0; p < NPFS; p++) {
            la[p] = g_logabs[b * NPFS + p];
            sg[p] = g_sign[b * NPFS + p];
            mx = fmaxf(mx, la[p]);
        }
        float val = 0.f;
        #pragma unroll
        for (int p = 0; p < NPFS; p++)
            val += sg[p] * expf(la[p] - mx);
        out[b]         = (val > 0.f) ? 1.f : ((val < 0.f) ? -1.f : 0.f);
        out[BATCH + b] = mx + logf(fabsf(val));
    }
}

// ---------------------------------------------------------------------------
extern "C" void kernel_launch(void* const* d_in, const int* in_sizes, int n_in,
                              void* d_out, int out_size) {
    const float* F   = (const float*)d_in[0];   // (4, 512, 512) fp32
    const int*   idx = (const int*)  d_in[1];   // (128, 256) int32
    float*       out = (float*)d_out;           // (2, 128) fp32

    const size_t shmem = (size_t)(L_ELEMS + 11 * NP) * sizeof(float); // ~144.5 KB
    cudaFuncSetAttribute(pf_kernel, cudaFuncAttributeMaxDynamicSharedMemorySize,
                         (int)shmem);

    pf_kernel<<<NMAT, NTHR, shmem>>>(F, idx);
    combine_kernel<<<1, 128>>>(out);
}